// round 6
// baseline (speedup 1.0000x reference)
#include <cuda_runtime.h>
#include <cuda_bf16.h>
#include <cstdint>

#define BATCH 8
#define NPTS  8192
#define NCTR  2048          // NPTS * 0.25
#define NSAMP 32
#define C0IN  67
#define C0    64
#define C1    64
#define C2    128
#define R2    0.25f         // radius^2

// ---------------- scratch (device globals; no allocation allowed) ----------------
__device__ int    g_ballidx[BATCH * NCTR * NSAMP];           // 2 MB
__device__ float  g_F0[(size_t)BATCH * NPTS * C0];           // 16 MB, layout (b, j, o)
__device__ float4 g_spos[(size_t)BATCH * NPTS];              // 1 MB, morton-sorted points

// ---------------- f32x2 packed helpers ----------------
__device__ __forceinline__ unsigned long long pk2(float lo, float hi) {
    unsigned long long r;
    asm("mov.b64 %0, {%1, %2};" : "=l"(r) : "f"(lo), "f"(hi));
    return r;
}
__device__ __forceinline__ unsigned long long pkb(float v) { return pk2(v, v); }
__device__ __forceinline__ void upk2(unsigned long long v, float& lo, float& hi) {
    asm("mov.b64 {%0, %1}, %2;" : "=f"(lo), "=f"(hi) : "l"(v));
}
#define F2FMA(d, a, b, c) asm("fma.rn.f32x2 %0, %1, %2, %3;" : "=l"(d) : "l"(a), "l"(b), "l"(c))
#define F2ADD(d, a, b)    asm("add.rn.f32x2 %0, %1, %2;"     : "=l"(d) : "l"(a), "l"(b))
#define F2MUL(d, a, b)    asm("mul.rn.f32x2 %0, %1, %2;"     : "=l"(d) : "l"(a), "l"(b))

// =====================================================================
// 0) Morton counting-sort per batch: g_spos[b][k] = (x,y,z, orig_idx).
//    Storage order within a cell is nondeterministic (atomics) but the
//    FPS OUTPUT is order-independent: dm values and tie-breaking use
//    original indices and exact per-point arithmetic only.
// =====================================================================
__device__ __forceinline__ int expand3(int v) {     // 3-bit -> bits 0,3,6
    return (v & 1) | ((v & 2) << 2) | ((v & 4) << 4);
}

__global__ void __launch_bounds__(512, 1)
sort_kernel(const float* __restrict__ pos)
{
    const int b = blockIdx.x, t = threadIdx.x;
    const int lane = t & 31, w = t >> 5;
    const float* pb = pos + (size_t)b * NPTS * 3;

    __shared__ float s_red[6][16];
    __shared__ int   s_hist[512];
    __shared__ int   s_wsum[16];
    __shared__ float s_bb[6];

    float x[16], y[16], z[16];
    float mnx = 1e30f, mny = 1e30f, mnz = 1e30f;
    float mxx = -1e30f, mxy = -1e30f, mxz = -1e30f;
#pragma unroll
    for (int k = 0; k < 16; k++) {
        int p = t * 16 + k;
        x[k] = pb[3 * p]; y[k] = pb[3 * p + 1]; z[k] = pb[3 * p + 2];
        mnx = fminf(mnx, x[k]); mxx = fmaxf(mxx, x[k]);
        mny = fminf(mny, y[k]); mxy = fmaxf(mxy, y[k]);
        mnz = fminf(mnz, z[k]); mxz = fmaxf(mxz, z[k]);
    }
#pragma unroll
    for (int o = 16; o > 0; o >>= 1) {
        mnx = fminf(mnx, __shfl_xor_sync(0xffffffffu, mnx, o));
        mny = fminf(mny, __shfl_xor_sync(0xffffffffu, mny, o));
        mnz = fminf(mnz, __shfl_xor_sync(0xffffffffu, mnz, o));
        mxx = fmaxf(mxx, __shfl_xor_sync(0xffffffffu, mxx, o));
        mxy = fmaxf(mxy, __shfl_xor_sync(0xffffffffu, mxy, o));
        mxz = fmaxf(mxz, __shfl_xor_sync(0xffffffffu, mxz, o));
    }
    if (lane == 0) {
        s_red[0][w] = mnx; s_red[1][w] = mny; s_red[2][w] = mnz;
        s_red[3][w] = mxx; s_red[4][w] = mxy; s_red[5][w] = mxz;
    }
    __syncthreads();
    if (w == 0 && lane < 6) {
        float v = s_red[lane][0];
        for (int i = 1; i < 16; i++)
            v = (lane < 3) ? fminf(v, s_red[lane][i]) : fmaxf(v, s_red[lane][i]);
        s_bb[lane] = v;
    }
    s_hist[t] = 0;
    __syncthreads();

    const float bnx = s_bb[0], bny = s_bb[1], bnz = s_bb[2];
    const float sx = 7.9999f / fmaxf(s_bb[3] - bnx, 1e-20f);
    const float sy = 7.9999f / fmaxf(s_bb[4] - bny, 1e-20f);
    const float sz = 7.9999f / fmaxf(s_bb[5] - bnz, 1e-20f);

    int key[16];
#pragma unroll
    for (int k = 0; k < 16; k++) {
        int qx = min(7, (int)((x[k] - bnx) * sx));
        int qy = min(7, (int)((y[k] - bny) * sy));
        int qz = min(7, (int)((z[k] - bnz) * sz));
        key[k] = expand3(qx) | (expand3(qy) << 1) | (expand3(qz) << 2);
        atomicAdd(&s_hist[key[k]], 1);
    }
    __syncthreads();

    // exclusive scan of 512 bins
    int v = s_hist[t];
    int inc = v;
#pragma unroll
    for (int o = 1; o < 32; o <<= 1) {
        int n = __shfl_up_sync(0xffffffffu, inc, o);
        if (lane >= o) inc += n;
    }
    if (lane == 31) s_wsum[w] = inc;
    __syncthreads();
    if (w == 0) {
        int ws = (lane < 16) ? s_wsum[lane] : 0;
        int wi = ws;
#pragma unroll
        for (int o = 1; o < 16; o <<= 1) {
            int n = __shfl_up_sync(0xffffffffu, wi, o);
            if (lane >= o) wi += n;
        }
        if (lane < 16) s_wsum[lane] = wi - ws;   // exclusive warp prefix
    }
    __syncthreads();
    int excl = inc - v + s_wsum[w];
    __syncthreads();
    s_hist[t] = excl;
    __syncthreads();

#pragma unroll
    for (int k = 0; k < 16; k++) {
        int d = atomicAdd(&s_hist[key[k]], 1);
        g_spos[(size_t)b * NPTS + d] =
            make_float4(x[k], y[k], z[k], __int_as_float(t * 16 + k));
    }
}

// =====================================================================
// 1) FPS with exact bbox pruning. One CTA per batch, 512 threads,
//    16 contiguous sorted points per thread; warp = 512-pt spatial chunk.
//    A warp skips the dm-update loop when d(c, bbox) provably exceeds
//    its current dm max:
//      d_rn(c,p) >= d_true(c,p)*(1-4e-7) >= dbb_true*(1-4e-7)
//                >= dbb_rn*(1-1e-6), so  dbb_rn > dmf*(1+1e-4)
//      implies d_rn(c,p) > dm_i for every point in the warp -> min()
//      leaves every dm unchanged, max & tie index unchanged. EXACT.
// =====================================================================
__global__ void __launch_bounds__(512, 1)
fps_kernel(const float* __restrict__ pos, float* __restrict__ new_xyz)
{
    const int b = blockIdx.x;
    const int t = threadIdx.x;
    const int lane = t & 31, w = t >> 5;
    const float* pb = pos + (size_t)b * NPTS * 3;
    const float4* sp = g_spos + (size_t)b * NPTS;

    unsigned long long xp[8], yp[8], zp[8];
    float dm[16];
    unsigned idxp[8];                         // two 13-bit orig indices per reg
    float bxn = 1e30f, byn = 1e30f, bzn = 1e30f;
    float bxx = -1e30f, byx = -1e30f, bzx = -1e30f;
#pragma unroll
    for (int k = 0; k < 8; k++) {
        float4 a = sp[t * 16 + 2 * k];
        float4 c = sp[t * 16 + 2 * k + 1];
        xp[k] = pk2(a.x, c.x);
        yp[k] = pk2(a.y, c.y);
        zp[k] = pk2(a.z, c.z);
        idxp[k] = (__float_as_uint(a.w) & 0xffffu) | (__float_as_uint(c.w) << 16);
        dm[2 * k] = 1e10f; dm[2 * k + 1] = 1e10f;
        bxn = fminf(bxn, fminf(a.x, c.x)); bxx = fmaxf(bxx, fmaxf(a.x, c.x));
        byn = fminf(byn, fminf(a.y, c.y)); byx = fmaxf(byx, fmaxf(a.y, c.y));
        bzn = fminf(bzn, fminf(a.z, c.z)); bzx = fmaxf(bzx, fmaxf(a.z, c.z));
    }
#pragma unroll
    for (int o = 16; o > 0; o >>= 1) {
        bxn = fminf(bxn, __shfl_xor_sync(0xffffffffu, bxn, o));
        byn = fminf(byn, __shfl_xor_sync(0xffffffffu, byn, o));
        bzn = fminf(bzn, __shfl_xor_sync(0xffffffffu, bzn, o));
        bxx = fmaxf(bxx, __shfl_xor_sync(0xffffffffu, bxx, o));
        byx = fmaxf(byx, __shfl_xor_sync(0xffffffffu, byx, o));
        bzx = fmaxf(bzx, __shfl_xor_sync(0xffffffffu, bzx, o));
    }

    __shared__ unsigned s_vhi[2][16], s_vlo[2][16];
    __shared__ float4   s_cord[2][16];

    float cx = pb[0], cy = pb[1], cz = pb[2];
    if (t == 0) {
        float* nz = new_xyz + (size_t)b * NCTR * 3;
        nz[0] = cx; nz[1] = cy; nz[2] = cz;
    }

    unsigned wmax_cur = __float_as_uint(1e10f);
    unsigned vlo_cur = 0;
    float4 ccache = make_float4(0.f, 0.f, 0.f, 0.f);

    for (int s = 1; s < NCTR; ++s) {
        const int buf = s & 1;

        // ---- exact bbox prune test (uniform per warp) ----
        float ddx = fmaxf(fmaxf(bxn - cx, cx - bxx), 0.0f);
        float ddy = fmaxf(fmaxf(byn - cy, cy - byx), 0.0f);
        float ddz = fmaxf(fmaxf(bzn - cz, cz - bzx), 0.0f);
        float dbb = ddx * ddx;
        dbb = fmaf(ddy, ddy, dbb);
        dbb = fmaf(ddz, ddz, dbb);
        bool active = !(dbb > __uint_as_float(wmax_cur) * 1.0001f);

        if (active) {
            const unsigned long long nx  = pkb(-cx);
            const unsigned long long ny  = pkb(-cy);
            const unsigned long long nzp = pkb(-cz);
            float m = 0.0f;
#pragma unroll
            for (int k = 0; k < 8; k++) {
                unsigned long long dx, dy, dz, sq;
                F2ADD(dx, xp[k], nx);
                F2ADD(dy, yp[k], ny);
                F2ADD(dz, zp[k], nzp);
                F2MUL(sq, dx, dx);
                F2FMA(sq, dy, dy, sq);
                F2FMA(sq, dz, dz, sq);         // == scalar fmaf(dz,dz,fmaf(dy,dy,dx*dx))
                float lo, hi; upk2(sq, lo, hi);
                dm[2 * k]     = fminf(dm[2 * k], lo);
                dm[2 * k + 1] = fminf(dm[2 * k + 1], hi);
                m = fmaxf(m, dm[2 * k]);
                m = fmaxf(m, dm[2 * k + 1]);
            }

            unsigned mb = __float_as_uint(m);
            unsigned wmax = __reduce_max_sync(0xffffffffu, mb);
            unsigned cand = 0xffffffffu;
            int kbest = 0;
            if (mb == wmax) {
#pragma unroll
                for (int j = 0; j < 16; j++) {
                    unsigned ij = (idxp[j >> 1] >> ((j & 1) * 16)) & 0xffffu;
                    if (__float_as_uint(dm[j]) == wmax && ij < cand) { cand = ij; kbest = j; }
                }
            }
            unsigned widx = __reduce_min_sync(0xffffffffu, cand);   // min orig idx among ties
            unsigned ob = __ballot_sync(0xffffffffu, cand == widx);
            int ol = __ffs((int)ob) - 1;
            int ps = __shfl_sync(0xffffffffu, t * 16 + kbest, ol);  // sorted pos of winner
            wmax_cur = wmax;
            vlo_cur = 8192u - widx;
            if (lane == 0) ccache = sp[ps];                         // L1-resident
        }

        if (lane == 0) {
            s_vhi[buf][w] = wmax_cur;
            s_vlo[buf][w] = vlo_cur;
            s_cord[buf][w] = ccache;
        }
        __syncthreads();                        // the ONLY barrier per step

        unsigned v = (lane < 16) ? s_vhi[buf][lane] : 0u;
        unsigned ghi = __reduce_max_sync(0xffffffffu, v);
        unsigned lo2 = (lane < 16 && v == ghi) ? s_vlo[buf][lane] : 0u;
        unsigned glo = __reduce_max_sync(0xffffffffu, lo2);
        unsigned wb2 = __ballot_sync(0xffffffffu, (v == ghi) && (lo2 == glo) && (lane < 16));
        int ww = __ffs((int)wb2) - 1;
        float4 cc = s_cord[buf][ww];            // uniform-address broadcast LDS
        cx = cc.x; cy = cc.y; cz = cc.z;
        if (t == 0) {
            float* nz = new_xyz + ((size_t)b * NCTR + s) * 3;
            nz[0] = cx; nz[1] = cy; nz[2] = cz;
        }
    }
}

// =====================================================================
// 2) F0(b, j, o) = sum_c w0[o, 3+c] * features[b, c, j]
// =====================================================================
__global__ void __launch_bounds__(128)
f0_kernel(const float* __restrict__ features, const float* __restrict__ w0)
{
    __shared__ float w0t[64][64];   // w0t[c][o]
    const int tid = threadIdx.x;
    const int b = blockIdx.y;
    const int j = blockIdx.x * 128 + tid;

    for (int i = tid; i < 64 * 64; i += 128) {
        int c = i >> 6, o = i & 63;
        w0t[c][o] = w0[o * C0IN + 3 + c];
    }
    __syncthreads();

    float acc[64];
#pragma unroll
    for (int o = 0; o < 64; o++) acc[o] = 0.0f;

    for (int c = 0; c < 64; c++) {
        float fc = features[((size_t)b * 64 + c) * NPTS + j];
#pragma unroll
        for (int o4 = 0; o4 < 64; o4 += 4) {
            float4 wv = *(const float4*)&w0t[c][o4];
            acc[o4 + 0] = fmaf(wv.x, fc, acc[o4 + 0]);
            acc[o4 + 1] = fmaf(wv.y, fc, acc[o4 + 1]);
            acc[o4 + 2] = fmaf(wv.z, fc, acc[o4 + 2]);
            acc[o4 + 3] = fmaf(wv.w, fc, acc[o4 + 3]);
        }
    }

    float* op = g_F0 + ((size_t)b * NPTS + j) * 64;
#pragma unroll
    for (int o4 = 0; o4 < 64; o4 += 4) {
        float4 v = make_float4(acc[o4], acc[o4 + 1], acc[o4 + 2], acc[o4 + 3]);
        *(float4*)(op + o4) = v;
    }
}

// =====================================================================
// 3) Ball query: WARP per center, ballot/popc ordered compaction,
//    early exit at 32 hits. Same fp formula as the passing version.
// =====================================================================
__global__ void __launch_bounds__(256)
ballq_kernel(const float* __restrict__ pos, const float* __restrict__ new_xyz)
{
    const int wid = blockIdx.x * 8 + (threadIdx.x >> 5);
    const int lane = threadIdx.x & 31;
    const int b = wid >> 11;

    const float* cz = new_xyz + (size_t)wid * 3;
    const float cx = cz[0], cy = cz[1], czz = cz[2];
    const float* pb = pos + (size_t)b * NPTS * 3;
    int* out = g_ballidx + (size_t)wid * NSAMP;

    int cnt = 0, first = -1;
    for (int j0 = 0; j0 < NPTS; j0 += 32) {
        int j = j0 + lane;
        float dx = pb[3 * j + 0] - cx;
        float dy = pb[3 * j + 1] - cy;
        float dz = pb[3 * j + 2] - czz;
        float d = fmaf(dz, dz, fmaf(dy, dy, dx * dx));
        bool hit = d < R2;
        unsigned bal = __ballot_sync(0xffffffffu, hit);
        if (bal) {
            if (first < 0) first = j0 + __ffs((int)bal) - 1;
            int pre = __popc(bal & ((1u << lane) - 1u));
            if (hit && cnt + pre < NSAMP) out[cnt + pre] = j;
            cnt += __popc(bal);
            if (cnt >= NSAMP) break;
        }
    }
    if (cnt < NSAMP) {
        int pad = (first < 0) ? 0 : first;
        if (lane >= cnt) out[lane] = pad;
    }
}

// =====================================================================
// 4) Fused grouped MLP + max pool (unchanged: 383us, occ 25%)
// =====================================================================
#define MLPT 512
#define XROW 260
#define SMEM_FLOATS (4096 + 8192 + 64*XROW + 64*XROW + 256 + 64 + 128)

__global__ void __launch_bounds__(MLPT, 1)
fused_mlp_kernel(const float* __restrict__ pos,
                 const float* __restrict__ new_xyz,
                 const float* __restrict__ w0, const float* __restrict__ b0,
                 const float* __restrict__ w1, const float* __restrict__ b1,
                 const float* __restrict__ w2, const float* __restrict__ b2,
                 float* __restrict__ out_feat)
{
    extern __shared__ float sm[];
    float* sW1 = sm;                       // [c][o] 64x64
    float* sW2 = sm + 4096;                // [c][o] 64x128
    float* sX0 = sm + 12288;               // [c][m] 64 x XROW
    float* sX1 = sm + 12288 + 64 * XROW;   // [c][m] 64 x XROW
    float4* sWXB = (float4*)(sm + 12288 + 128 * XROW);   // 64 x {w0x,w0y,w0z,b0}
    float* sB1 = sm + 12288 + 128 * XROW + 256;
    float* sB2 = sB1 + 64;

    const int tid = threadIdx.x;
    const int b = blockIdx.x >> 8;
    const int s0 = (blockIdx.x & 255) * 8;

    for (int i = tid; i < 4096; i += MLPT) {
        int c = i >> 6, o = i & 63;
        sW1[c * 64 + o] = w1[o * 64 + c];
    }
    for (int i = tid; i < 8192; i += MLPT) {
        int c = i >> 7, o = i & 127;
        sW2[c * 128 + o] = w2[o * 64 + c];
    }
    if (tid < 64) {
        sWXB[tid] = make_float4(w0[tid * C0IN + 0], w0[tid * C0IN + 1],
                                w0[tid * C0IN + 2], b0[tid]);
        sB1[tid] = b1[tid];
    }
    if (tid < 128) sB2[tid] = b2[tid];
    __syncthreads();

    {
        const int r = tid >> 1;
        const int h = tid & 1;
        const int o0 = h * 32;
        const int ci = r >> 5, k = r & 31;
        const int sg = s0 + ci;
        const int j = g_ballidx[(((size_t)b * NCTR + sg) << 5) + k];

        const float* pp = pos + ((size_t)b * NPTS + j) * 3;
        const float* cz = new_xyz + ((size_t)b * NCTR + sg) * 3;
        float rx = pp[0] - cz[0];
        float ry = pp[1] - cz[1];
        float rz = pp[2] - cz[2];
        const float* fp = g_F0 + ((size_t)b * NPTS + j) * 64 + o0;

#pragma unroll
        for (int o4 = 0; o4 < 32; o4 += 4) {
            float4 f = *(const float4*)(fp + o4);
            float fv[4] = { f.x, f.y, f.z, f.w };
#pragma unroll
            for (int i = 0; i < 4; i++) {
                float4 wb = sWXB[o0 + o4 + i];
                float v = fv[i] + wb.x * rx + wb.y * ry + wb.z * rz + wb.w;
                sX0[(o0 + o4 + i) * XROW + r] = fmaxf(v, 0.0f);
            }
        }
    }
    __syncthreads();

    const int tm = tid & 63, tn = tid >> 6;
    const int m0 = tm * 4;

    {
        const int n0 = tn * 8;
        unsigned long long acc2[16];
#pragma unroll
        for (int i = 0; i < 16; i++) acc2[i] = 0ULL;

#pragma unroll 8
        for (int c = 0; c < 64; c++) {
            float4 a  = *(const float4*)&sX0[c * XROW + m0];
            float4 bA = *(const float4*)&sW1[c * 64 + n0];
            float4 bB = *(const float4*)&sW1[c * 64 + n0 + 4];
            unsigned long long bp[4] = { pk2(bA.x, bA.y), pk2(bA.z, bA.w),
                                         pk2(bB.x, bB.y), pk2(bB.z, bB.w) };
            unsigned long long ap[4] = { pkb(a.x), pkb(a.y), pkb(a.z), pkb(a.w) };
#pragma unroll
            for (int i = 0; i < 4; i++)
#pragma unroll
                for (int jp = 0; jp < 4; jp++)
                    F2FMA(acc2[i * 4 + jp], ap[i], bp[jp], acc2[i * 4 + jp]);
        }

#pragma unroll
        for (int jp = 0; jp < 4; jp++) {
            float lo[4], hi[4];
#pragma unroll
            for (int i = 0; i < 4; i++) upk2(acc2[i * 4 + jp], lo[i], hi[i]);
            float bb0 = sB1[n0 + 2 * jp], bb1 = sB1[n0 + 2 * jp + 1];
            float4 v0, v1;
            v0.x = fmaxf(lo[0] + bb0, 0.0f); v0.y = fmaxf(lo[1] + bb0, 0.0f);
            v0.z = fmaxf(lo[2] + bb0, 0.0f); v0.w = fmaxf(lo[3] + bb0, 0.0f);
            v1.x = fmaxf(hi[0] + bb1, 0.0f); v1.y = fmaxf(hi[1] + bb1, 0.0f);
            v1.z = fmaxf(hi[2] + bb1, 0.0f); v1.w = fmaxf(hi[3] + bb1, 0.0f);
            *(float4*)&sX1[(n0 + 2 * jp)     * XROW + m0] = v0;
            *(float4*)&sX1[(n0 + 2 * jp + 1) * XROW + m0] = v1;
        }
    }
    __syncthreads();

    {
        const int n2 = tn * 16;
        unsigned long long acc2[32];
#pragma unroll
        for (int i = 0; i < 32; i++) acc2[i] = 0ULL;

#pragma unroll 4
        for (int c = 0; c < 64; c++) {
            float4 a = *(const float4*)&sX1[c * XROW + m0];
            unsigned long long ap[4] = { pkb(a.x), pkb(a.y), pkb(a.z), pkb(a.w) };
            unsigned long long bp[8];
#pragma unroll
            for (int q = 0; q < 4; q++) {
                float4 bb = *(const float4*)&sW2[c * 128 + n2 + 4 * q];
                bp[2 * q]     = pk2(bb.x, bb.y);
                bp[2 * q + 1] = pk2(bb.z, bb.w);
            }
#pragma unroll
            for (int i = 0; i < 4; i++)
#pragma unroll
                for (int jp = 0; jp < 8; jp++)
                    F2FMA(acc2[i * 8 + jp], ap[i], bp[jp], acc2[i * 8 + jp]);
        }

        const int center = tm >> 3;
#pragma unroll
        for (int jp = 0; jp < 8; jp++) {
            float lo[4], hi[4];
#pragma unroll
            for (int i = 0; i < 4; i++) upk2(acc2[i * 8 + jp], lo[i], hi[i]);
            float vlo = fmaxf(fmaxf(lo[0], lo[1]), fmaxf(lo[2], lo[3]));
            float vhi = fmaxf(fmaxf(hi[0], hi[1]), fmaxf(hi[2], hi[3]));
            vlo = fmaxf(vlo, __shfl_xor_sync(0xffffffffu, vlo, 1));
            vhi = fmaxf(vhi, __shfl_xor_sync(0xffffffffu, vhi, 1));
            vlo = fmaxf(vlo, __shfl_xor_sync(0xffffffffu, vlo, 2));
            vhi = fmaxf(vhi, __shfl_xor_sync(0xffffffffu, vhi, 2));
            vlo = fmaxf(vlo, __shfl_xor_sync(0xffffffffu, vlo, 4));
            vhi = fmaxf(vhi, __shfl_xor_sync(0xffffffffu, vhi, 4));
            if ((tm & 7) == 0) {
                int n = n2 + 2 * jp;
                out_feat[((size_t)b * C2 + n)     * NCTR + (s0 + center)] =
                    fmaxf(vlo + sB2[n], 0.0f);
                out_feat[((size_t)b * C2 + n + 1) * NCTR + (s0 + center)] =
                    fmaxf(vhi + sB2[n + 1], 0.0f);
            }
        }
    }
}

// =====================================================================
extern "C" void kernel_launch(void* const* d_in, const int* in_sizes, int n_in,
                              void* d_out, int out_size)
{
    const float* pos      = (const float*)d_in[0];
    const float* features = (const float*)d_in[1];
    const float* w0       = (const float*)d_in[2];
    const float* b0       = (const float*)d_in[3];
    const float* w1       = (const float*)d_in[4];
    const float* b1       = (const float*)d_in[5];
    const float* w2       = (const float*)d_in[6];
    const float* b2       = (const float*)d_in[7];

    float* out = (float*)d_out;
    float* new_xyz  = out;                               // (8, 2048, 3)
    float* out_feat = out + (size_t)BATCH * NCTR * 3;    // (8, 128, 2048)

    sort_kernel<<<BATCH, 512>>>(pos);
    fps_kernel<<<BATCH, 512>>>(pos, new_xyz);
    f0_kernel<<<dim3(NPTS / 128, BATCH), 128>>>(features, w0);
    ballq_kernel<<<(BATCH * NCTR) / 8, 256>>>(pos, new_xyz);

    cudaFuncSetAttribute(fused_mlp_kernel,
                         cudaFuncAttributeMaxDynamicSharedMemorySize,
                         SMEM_FLOATS * sizeof(float));
    fused_mlp_kernel<<<BATCH * NCTR / 8, MLPT, SMEM_FLOATS * sizeof(float)>>>(
        pos, new_xyz, w0, b0, w1, b1, w2, b2, out_feat);
}

// round 7
// speedup vs baseline: 1.2978x; 1.2978x over previous
#include <cuda_runtime.h>
#include <cuda_bf16.h>
#include <cstdint>

#define BATCH 8
#define NPTS  8192
#define NCTR  2048          // NPTS * 0.25
#define NSAMP 32
#define C0IN  67
#define C0    64
#define C1    64
#define C2    128
#define R2    0.25f         // radius^2

// ---------------- scratch (device globals; no allocation allowed) ----------------
__device__ int   g_ballidx[BATCH * NCTR * NSAMP];            // 2 MB
__device__ float g_F0[(size_t)BATCH * NPTS * C0];            // 16 MB, layout (b, j, o)

// ---------------- f32x2 packed helpers ----------------
__device__ __forceinline__ unsigned long long pk2(float lo, float hi) {
    unsigned long long r;
    asm("mov.b64 %0, {%1, %2};" : "=l"(r) : "f"(lo), "f"(hi));
    return r;
}
__device__ __forceinline__ unsigned long long pkb(float v) { return pk2(v, v); }
__device__ __forceinline__ void upk2(unsigned long long v, float& lo, float& hi) {
    asm("mov.b64 {%0, %1}, %2;" : "=f"(lo), "=f"(hi) : "l"(v));
}
#define F2FMA(d, a, b, c) asm("fma.rn.f32x2 %0, %1, %2, %3;" : "=l"(d) : "l"(a), "l"(b), "l"(c))
#define F2ADD(d, a, b)    asm("add.rn.f32x2 %0, %1, %2;"     : "=l"(d) : "l"(a), "l"(b))
#define F2MUL(d, a, b)    asm("mul.rn.f32x2 %0, %1, %2;"     : "=l"(d) : "l"(a), "l"(b))

// =====================================================================
// 1) FPS: one CTA per batch, 256 threads (8 warps), 32 pts/thread,
//    f32x2 packed distance update. One barrier per step, parity
//    double-buffered per-warp (val, 8192-idx) pairs; every warp
//    redundantly reduces the 8 warp results (no second barrier).
// =====================================================================
__global__ void __launch_bounds__(256, 1)
fps_kernel(const float* __restrict__ pos, float* __restrict__ new_xyz)
{
    const int b = blockIdx.x;
    const int t = threadIdx.x;
    const int lane = t & 31, w = t >> 5;
    const float* pb = pos + (size_t)b * NPTS * 3;

    unsigned long long xp[16], yp[16], zp[16];
    float dm[32];
#pragma unroll
    for (int k = 0; k < 16; k++) {
        int p0 = t + (2 * k) * 256;
        int p1 = p0 + 256;
        xp[k] = pk2(pb[3 * p0 + 0], pb[3 * p1 + 0]);
        yp[k] = pk2(pb[3 * p0 + 1], pb[3 * p1 + 1]);
        zp[k] = pk2(pb[3 * p0 + 2], pb[3 * p1 + 2]);
        dm[2 * k] = 1e10f; dm[2 * k + 1] = 1e10f;
    }

    __shared__ unsigned s_vhi[2][8];     // [parity][warp] distance bits
    __shared__ unsigned s_vlo[2][8];     // [parity][warp] 8192 - idx

    float cx = pb[0], cy = pb[1], cz = pb[2];
    if (t == 0) {
        float* nz = new_xyz + (size_t)b * NCTR * 3;
        nz[0] = cx; nz[1] = cy; nz[2] = cz;
    }

    for (int s = 1; s < NCTR; ++s) {
        const int buf = s & 1;

        // ---- distance update (f32x2) + per-thread max ----
        const unsigned long long nx  = pkb(-cx);
        const unsigned long long ny  = pkb(-cy);
        const unsigned long long nzp = pkb(-cz);
        float m = 0.0f;
#pragma unroll
        for (int k = 0; k < 16; k++) {
            unsigned long long dx, dy, dz, sq;
            F2ADD(dx, xp[k], nx);
            F2ADD(dy, yp[k], ny);
            F2ADD(dz, zp[k], nzp);
            F2MUL(sq, dx, dx);
            F2FMA(sq, dy, dy, sq);
            F2FMA(sq, dz, dz, sq);          // == scalar fmaf(dz,dz,fmaf(dy,dy,dx*dx))
            float lo, hi; upk2(sq, lo, hi);
            dm[2 * k]     = fminf(dm[2 * k], lo);
            dm[2 * k + 1] = fminf(dm[2 * k + 1], hi);
            m = fmaxf(m, dm[2 * k]);
            m = fmaxf(m, dm[2 * k + 1]);
        }

        // ---- warp reduce: max value, min index on ties ----
        unsigned mb = __float_as_uint(m);            // d >= 0: order-preserving
        unsigned wmax = __reduce_max_sync(0xffffffffu, mb);
        unsigned cand = 0xffffffffu;
        if (mb == wmax) {
#pragma unroll
            for (int j = 31; j >= 0; j--)
                if (__float_as_uint(dm[j]) == wmax) cand = (unsigned)((j << 8) + t);
        }
        unsigned widx = __reduce_min_sync(0xffffffffu, cand);
        if (lane == 0) {
            s_vhi[buf][w] = wmax;
            s_vlo[buf][w] = 8192u - widx;            // larger = smaller index
        }
        __syncthreads();                             // the ONLY barrier per step

        // ---- every warp redundantly reduces the 8 warp pairs ----
        unsigned v   = (lane < 8) ? s_vhi[buf][lane] : 0u;
        unsigned ghi = __reduce_max_sync(0xffffffffu, v);
        unsigned lo2 = (lane < 8 && v == ghi) ? s_vlo[buf][lane] : 0u;
        unsigned glo = __reduce_max_sync(0xffffffffu, lo2);
        unsigned gidx = 8192u - glo;

        const float* pp = pb + 3 * (size_t)gidx;     // broadcast LDG, L1-hit
        cx = pp[0]; cy = pp[1]; cz = pp[2];
        if (t == 0) {
            float* nz = new_xyz + ((size_t)b * NCTR + s) * 3;
            nz[0] = cx; nz[1] = cy; nz[2] = cz;
        }
    }
}

// =====================================================================
// 2) F0(b, j, o) = sum_c w0[o, 3+c] * features[b, c, j]
// =====================================================================
__global__ void __launch_bounds__(128)
f0_kernel(const float* __restrict__ features, const float* __restrict__ w0)
{
    __shared__ float w0t[64][64];   // w0t[c][o]
    const int tid = threadIdx.x;
    const int b = blockIdx.y;
    const int j = blockIdx.x * 128 + tid;

    for (int i = tid; i < 64 * 64; i += 128) {
        int c = i >> 6, o = i & 63;
        w0t[c][o] = w0[o * C0IN + 3 + c];
    }
    __syncthreads();

    float acc[64];
#pragma unroll
    for (int o = 0; o < 64; o++) acc[o] = 0.0f;

    for (int c = 0; c < 64; c++) {
        float fc = features[((size_t)b * 64 + c) * NPTS + j];
#pragma unroll
        for (int o4 = 0; o4 < 64; o4 += 4) {
            float4 wv = *(const float4*)&w0t[c][o4];
            acc[o4 + 0] = fmaf(wv.x, fc, acc[o4 + 0]);
            acc[o4 + 1] = fmaf(wv.y, fc, acc[o4 + 1]);
            acc[o4 + 2] = fmaf(wv.z, fc, acc[o4 + 2]);
            acc[o4 + 3] = fmaf(wv.w, fc, acc[o4 + 3]);
        }
    }

    float* op = g_F0 + ((size_t)b * NPTS + j) * 64;
#pragma unroll
    for (int o4 = 0; o4 < 64; o4 += 4) {
        float4 v = make_float4(acc[o4], acc[o4 + 1], acc[o4 + 2], acc[o4 + 3]);
        *(float4*)(op + o4) = v;
    }
}

// =====================================================================
// 3) Ball query: thread per center (round-4 version: early exit wins)
// =====================================================================
__global__ void __launch_bounds__(128)
ballq_kernel(const float* __restrict__ pos, const float* __restrict__ new_xyz)
{
    const int gid = blockIdx.x * 128 + threadIdx.x;
    const int b = gid >> 11;          // / 2048

    const float* cz = new_xyz + (size_t)gid * 3;
    const float cx = cz[0], cy = cz[1], czz = cz[2];
    const float* pb = pos + (size_t)b * NPTS * 3;
    int* out = g_ballidx + (size_t)gid * NSAMP;

    int cnt = 0;
    int first = 0;
    for (int j = 0; j < NPTS; j++) {
        float dx = pb[3 * j + 0] - cx;
        float dy = pb[3 * j + 1] - cy;
        float dz = pb[3 * j + 2] - czz;
        float d = fmaf(dz, dz, fmaf(dy, dy, dx * dx));
        if (d < R2) {
            if (cnt == 0) first = j;
            out[cnt++] = j;
            if (cnt == NSAMP) break;
        }
    }
    for (int k = cnt; k < NSAMP; k++) out[k] = first;
}

// =====================================================================
// 4) Fused grouped MLP + max pool: 512 threads, 8 centers (256 rows)
//    per block. f32x2 GEMM cores. (unchanged: 383us)
// =====================================================================
#define MLPT 512
#define XROW 260
#define SMEM_FLOATS (4096 + 8192 + 64*XROW + 64*XROW + 256 + 64 + 128)

__global__ void __launch_bounds__(MLPT, 1)
fused_mlp_kernel(const float* __restrict__ pos,
                 const float* __restrict__ new_xyz,
                 const float* __restrict__ w0, const float* __restrict__ b0,
                 const float* __restrict__ w1, const float* __restrict__ b1,
                 const float* __restrict__ w2, const float* __restrict__ b2,
                 float* __restrict__ out_feat)
{
    extern __shared__ float sm[];
    float* sW1 = sm;                       // [c][o] 64x64
    float* sW2 = sm + 4096;                // [c][o] 64x128
    float* sX0 = sm + 12288;               // [c][m] 64 x XROW
    float* sX1 = sm + 12288 + 64 * XROW;   // [c][m] 64 x XROW
    float4* sWXB = (float4*)(sm + 12288 + 128 * XROW);   // 64 x {w0x,w0y,w0z,b0}
    float* sB1 = sm + 12288 + 128 * XROW + 256;
    float* sB2 = sB1 + 64;

    const int tid = threadIdx.x;
    const int b = blockIdx.x >> 8;
    const int s0 = (blockIdx.x & 255) * 8;

    for (int i = tid; i < 4096; i += MLPT) {
        int c = i >> 6, o = i & 63;
        sW1[c * 64 + o] = w1[o * 64 + c];
    }
    for (int i = tid; i < 8192; i += MLPT) {
        int c = i >> 7, o = i & 127;
        sW2[c * 128 + o] = w2[o * 64 + c];
    }
    if (tid < 64) {
        sWXB[tid] = make_float4(w0[tid * C0IN + 0], w0[tid * C0IN + 1],
                                w0[tid * C0IN + 2], b0[tid]);
        sB1[tid] = b1[tid];
    }
    if (tid < 128) sB2[tid] = b2[tid];
    __syncthreads();

    {
        const int r = tid >> 1;
        const int h = tid & 1;
        const int o0 = h * 32;
        const int ci = r >> 5, k = r & 31;
        const int sg = s0 + ci;
        const int j = g_ballidx[(((size_t)b * NCTR + sg) << 5) + k];

        const float* pp = pos + ((size_t)b * NPTS + j) * 3;
        const float* cz = new_xyz + ((size_t)b * NCTR + sg) * 3;
        float rx = pp[0] - cz[0];
        float ry = pp[1] - cz[1];
        float rz = pp[2] - cz[2];
        const float* fp = g_F0 + ((size_t)b * NPTS + j) * 64 + o0;

#pragma unroll
        for (int o4 = 0; o4 < 32; o4 += 4) {
            float4 f = *(const float4*)(fp + o4);
            float fv[4] = { f.x, f.y, f.z, f.w };
#pragma unroll
            for (int i = 0; i < 4; i++) {
                float4 wb = sWXB[o0 + o4 + i];
                float v = fv[i] + wb.x * rx + wb.y * ry + wb.z * rz + wb.w;
                sX0[(o0 + o4 + i) * XROW + r] = fmaxf(v, 0.0f);
            }
        }
    }
    __syncthreads();

    const int tm = tid & 63, tn = tid >> 6;
    const int m0 = tm * 4;

    {
        const int n0 = tn * 8;
        unsigned long long acc2[16];
#pragma unroll
        for (int i = 0; i < 16; i++) acc2[i] = 0ULL;

#pragma unroll 8
        for (int c = 0; c < 64; c++) {
            float4 a  = *(const float4*)&sX0[c * XROW + m0];
            float4 bA = *(const float4*)&sW1[c * 64 + n0];
            float4 bB = *(const float4*)&sW1[c * 64 + n0 + 4];
            unsigned long long bp[4] = { pk2(bA.x, bA.y), pk2(bA.z, bA.w),
                                         pk2(bB.x, bB.y), pk2(bB.z, bB.w) };
            unsigned long long ap[4] = { pkb(a.x), pkb(a.y), pkb(a.z), pkb(a.w) };
#pragma unroll
            for (int i = 0; i < 4; i++)
#pragma unroll
                for (int jp = 0; jp < 4; jp++)
                    F2FMA(acc2[i * 4 + jp], ap[i], bp[jp], acc2[i * 4 + jp]);
        }

#pragma unroll
        for (int jp = 0; jp < 4; jp++) {
            float lo[4], hi[4];
#pragma unroll
            for (int i = 0; i < 4; i++) upk2(acc2[i * 4 + jp], lo[i], hi[i]);
            float bb0 = sB1[n0 + 2 * jp], bb1 = sB1[n0 + 2 * jp + 1];
            float4 v0, v1;
            v0.x = fmaxf(lo[0] + bb0, 0.0f); v0.y = fmaxf(lo[1] + bb0, 0.0f);
            v0.z = fmaxf(lo[2] + bb0, 0.0f); v0.w = fmaxf(lo[3] + bb0, 0.0f);
            v1.x = fmaxf(hi[0] + bb1, 0.0f); v1.y = fmaxf(hi[1] + bb1, 0.0f);
            v1.z = fmaxf(hi[2] + bb1, 0.0f); v1.w = fmaxf(hi[3] + bb1, 0.0f);
            *(float4*)&sX1[(n0 + 2 * jp)     * XROW + m0] = v0;
            *(float4*)&sX1[(n0 + 2 * jp + 1) * XROW + m0] = v1;
        }
    }
    __syncthreads();

    {
        const int n2 = tn * 16;
        unsigned long long acc2[32];
#pragma unroll
        for (int i = 0; i < 32; i++) acc2[i] = 0ULL;

#pragma unroll 4
        for (int c = 0; c < 64; c++) {
            float4 a = *(const float4*)&sX1[c * XROW + m0];
            unsigned long long ap[4] = { pkb(a.x), pkb(a.y), pkb(a.z), pkb(a.w) };
            unsigned long long bp[8];
#pragma unroll
            for (int q = 0; q < 4; q++) {
                float4 bb = *(const float4*)&sW2[c * 128 + n2 + 4 * q];
                bp[2 * q]     = pk2(bb.x, bb.y);
                bp[2 * q + 1] = pk2(bb.z, bb.w);
            }
#pragma unroll
            for (int i = 0; i < 4; i++)
#pragma unroll
                for (int jp = 0; jp < 8; jp++)
                    F2FMA(acc2[i * 8 + jp], ap[i], bp[jp], acc2[i * 8 + jp]);
        }

        const int center = tm >> 3;
#pragma unroll
        for (int jp = 0; jp < 8; jp++) {
            float lo[4], hi[4];
#pragma unroll
            for (int i = 0; i < 4; i++) upk2(acc2[i * 8 + jp], lo[i], hi[i]);
            float vlo = fmaxf(fmaxf(lo[0], lo[1]), fmaxf(lo[2], lo[3]));
            float vhi = fmaxf(fmaxf(hi[0], hi[1]), fmaxf(hi[2], hi[3]));
            vlo = fmaxf(vlo, __shfl_xor_sync(0xffffffffu, vlo, 1));
            vhi = fmaxf(vhi, __shfl_xor_sync(0xffffffffu, vhi, 1));
            vlo = fmaxf(vlo, __shfl_xor_sync(0xffffffffu, vlo, 2));
            vhi = fmaxf(vhi, __shfl_xor_sync(0xffffffffu, vhi, 2));
            vlo = fmaxf(vlo, __shfl_xor_sync(0xffffffffu, vlo, 4));
            vhi = fmaxf(vhi, __shfl_xor_sync(0xffffffffu, vhi, 4));
            if ((tm & 7) == 0) {
                int n = n2 + 2 * jp;
                out_feat[((size_t)b * C2 + n)     * NCTR + (s0 + center)] =
                    fmaxf(vlo + sB2[n], 0.0f);
                out_feat[((size_t)b * C2 + n + 1) * NCTR + (s0 + center)] =
                    fmaxf(vhi + sB2[n + 1], 0.0f);
            }
        }
    }
}

// =====================================================================
extern "C" void kernel_launch(void* const* d_in, const int* in_sizes, int n_in,
                              void* d_out, int out_size)
{
    const float* pos      = (const float*)d_in[0];
    const float* features = (const float*)d_in[1];
    const float* w0       = (const float*)d_in[2];
    const float* b0       = (const float*)d_in[3];
    const float* w1       = (const float*)d_in[4];
    const float* b1       = (const float*)d_in[5];
    const float* w2       = (const float*)d_in[6];
    const float* b2       = (const float*)d_in[7];

    float* out = (float*)d_out;
    float* new_xyz  = out;                               // (8, 2048, 3)
    float* out_feat = out + (size_t)BATCH * NCTR * 3;    // (8, 128, 2048)

    fps_kernel<<<BATCH, 256>>>(pos, new_xyz);
    f0_kernel<<<dim3(NPTS / 128, BATCH), 128>>>(features, w0);
    ballq_kernel<<<(BATCH * NCTR) / 128, 128>>>(pos, new_xyz);

    cudaFuncSetAttribute(fused_mlp_kernel,
                         cudaFuncAttributeMaxDynamicSharedMemorySize,
                         SMEM_FLOATS * sizeof(float));
    fused_mlp_kernel<<<BATCH * NCTR / 8, MLPT, SMEM_FLOATS * sizeof(float)>>>(
        pos, new_xyz, w0, b0, w1, b1, w2, b2, out_feat);
}

// round 8
// speedup vs baseline: 1.4684x; 1.1314x over previous
#include <cuda_runtime.h>
#include <cuda_bf16.h>
#include <cstdint>

#define BATCH 8
#define NPTS  8192
#define NCTR  2048          // NPTS * 0.25
#define NSAMP 32
#define C0IN  67
#define C2    128
#define R2    0.25f         // radius^2

// ---------------- scratch (device globals; no allocation allowed) ----------------
__device__ float    g_F0[(size_t)BATCH * NPTS * 64];     // 16 MB, layout (b, j, o)
__device__ unsigned g_progress[BATCH];                   // centers published per batch
__device__ unsigned g_f0done[BATCH];                     // f0 chunks done per batch (8 = ready)

// ---------------- f32x2 packed helpers ----------------
__device__ __forceinline__ unsigned long long pk2(float lo, float hi) {
    unsigned long long r;
    asm("mov.b64 %0, {%1, %2};" : "=l"(r) : "f"(lo), "f"(hi));
    return r;
}
__device__ __forceinline__ unsigned long long pkb(float v) { return pk2(v, v); }
__device__ __forceinline__ void upk2(unsigned long long v, float& lo, float& hi) {
    asm("mov.b64 {%0, %1}, %2;" : "=f"(lo), "=f"(hi) : "l"(v));
}
#define F2FMA(d, a, b, c) asm("fma.rn.f32x2 %0, %1, %2, %3;" : "=l"(d) : "l"(a), "l"(b), "l"(c))
#define F2ADD(d, a, b)    asm("add.rn.f32x2 %0, %1, %2;"     : "=l"(d) : "l"(a), "l"(b))
#define F2MUL(d, a, b)    asm("mul.rn.f32x2 %0, %1, %2;"     : "=l"(d) : "l"(a), "l"(b))

// ---------------- acquire/release helpers ----------------
__device__ __forceinline__ unsigned ld_acq(const unsigned* p) {
    unsigned v;
    asm volatile("ld.acquire.gpu.global.u32 %0, [%1];" : "=r"(v) : "l"(p) : "memory");
    return v;
}
__device__ __forceinline__ void st_rel(unsigned* p, unsigned v) {
    asm volatile("st.release.gpu.global.u32 [%0], %1;" :: "l"(p), "r"(v) : "memory");
}

// =====================================================================
// reset: clear the inter-block flags (needed per graph replay)
// =====================================================================
__global__ void reset_kernel()
{
    if (threadIdx.x < BATCH) {
        g_progress[threadIdx.x] = 0;
        g_f0done[threadIdx.x]  = 0;
    }
}

// =====================================================================
// mega-kernel: bid 0-7 FPS | bid 8-71 F0 | bid 72+ ballq+MLP workers
// =====================================================================
#define MLPT 512
#define XROW 260
#define SMEM_FLOATS (4096 + 8192 + 64*XROW + 64*XROW + 256 + 64 + 128)
#define GRID_TOTAL (8 + 64 + BATCH * NCTR / 8)

__global__ void __launch_bounds__(MLPT, 1)
mega_kernel(const float* __restrict__ pos,
            const float* __restrict__ features,
            const float* __restrict__ w0, const float* __restrict__ b0,
            const float* __restrict__ w1, const float* __restrict__ b1,
            const float* __restrict__ w2, const float* __restrict__ b2,
            float* __restrict__ new_xyz,
            float* __restrict__ out_feat)
{
    const int bid = blockIdx.x;
    const int tid = threadIdx.x;
    extern __shared__ float sm[];

    // =================================================================
    // ROLE 1: FPS (round-4 512-thread version + amortized publish)
    // =================================================================
    if (bid < 8) {
        const int b = bid;
        const int t = tid;
        const int lane = t & 31, w = t >> 5;
        const float* pb = pos + (size_t)b * NPTS * 3;

        unsigned long long xp[8], yp[8], zp[8];
        float dm[16];
#pragma unroll
        for (int k = 0; k < 8; k++) {
            int p0 = t + (2 * k) * 512;
            int p1 = p0 + 512;
            xp[k] = pk2(pb[3 * p0 + 0], pb[3 * p1 + 0]);
            yp[k] = pk2(pb[3 * p0 + 1], pb[3 * p1 + 1]);
            zp[k] = pk2(pb[3 * p0 + 2], pb[3 * p1 + 2]);
            dm[2 * k] = 1e10f; dm[2 * k + 1] = 1e10f;
        }

        __shared__ unsigned s_vhi[2][16];
        __shared__ unsigned s_vlo[2][16];

        float cx = pb[0], cy = pb[1], cz = pb[2];
        if (t == 0) {
            float* nz = new_xyz + (size_t)b * NCTR * 3;
            nz[0] = cx; nz[1] = cy; nz[2] = cz;
        }

        for (int s = 1; s < NCTR; ++s) {
            const int buf = s & 1;

            const unsigned long long nx  = pkb(-cx);
            const unsigned long long ny  = pkb(-cy);
            const unsigned long long nzp = pkb(-cz);
            float m = 0.0f;
#pragma unroll
            for (int k = 0; k < 8; k++) {
                unsigned long long dx, dy, dz, sq;
                F2ADD(dx, xp[k], nx);
                F2ADD(dy, yp[k], ny);
                F2ADD(dz, zp[k], nzp);
                F2MUL(sq, dx, dx);
                F2FMA(sq, dy, dy, sq);
                F2FMA(sq, dz, dz, sq);      // == scalar fmaf chain (exact)
                float lo, hi; upk2(sq, lo, hi);
                dm[2 * k]     = fminf(dm[2 * k], lo);
                dm[2 * k + 1] = fminf(dm[2 * k + 1], hi);
                m = fmaxf(m, dm[2 * k]);
                m = fmaxf(m, dm[2 * k + 1]);
            }

            unsigned mb = __float_as_uint(m);
            unsigned wmax = __reduce_max_sync(0xffffffffu, mb);
            unsigned cand = 0xffffffffu;
            if (mb == wmax) {
#pragma unroll
                for (int j = 15; j >= 0; j--)
                    if (__float_as_uint(dm[j]) == wmax) cand = (unsigned)((j << 9) + t);
            }
            unsigned widx = __reduce_min_sync(0xffffffffu, cand);
            if (lane == 0) {
                s_vhi[buf][w] = wmax;
                s_vlo[buf][w] = 8192u - widx;
            }
            __syncthreads();

            unsigned v   = (lane < 16) ? s_vhi[buf][lane] : 0u;
            unsigned ghi = __reduce_max_sync(0xffffffffu, v);
            unsigned lo2 = (lane < 16 && v == ghi) ? s_vlo[buf][lane] : 0u;
            unsigned glo = __reduce_max_sync(0xffffffffu, lo2);
            unsigned gidx = 8192u - glo;

            const float* pp = pb + 3 * (size_t)gidx;
            cx = pp[0]; cy = pp[1]; cz = pp[2];
            if (t == 0) {
                float* nz = new_xyz + ((size_t)b * NCTR + s) * 3;
                nz[0] = cx; nz[1] = cy; nz[2] = cz;
                if ((s & 7) == 7) st_rel(&g_progress[b], (unsigned)(s + 1));
            }
        }
        return;
    }

    // =================================================================
    // ROLE 2: F0 precompute. 64 blocks: batch = fb>>3, 1024-pt chunk.
    // F0(b, j, o) = sum_c w0[o, 3+c] * features[b, c, j]
    // =================================================================
    if (bid < 72) {
        const int fb = bid - 8;
        const int b = fb >> 3;
        const int j0 = (fb & 7) * 1024;
        float (*w0t)[64] = (float(*)[64])sm;     // [c][o]

        for (int i = tid; i < 64 * 64; i += MLPT) {
            int c = i >> 6, o = i & 63;
            w0t[c][o] = w0[o * C0IN + 3 + c];
        }
        __syncthreads();

#pragma unroll
        for (int rep = 0; rep < 2; rep++) {
            const int j = j0 + rep * 512 + tid;
            float acc[64];
#pragma unroll
            for (int o = 0; o < 64; o++) acc[o] = 0.0f;

            for (int c = 0; c < 64; c++) {
                float fc = features[((size_t)b * 64 + c) * NPTS + j];
#pragma unroll
                for (int o4 = 0; o4 < 64; o4 += 4) {
                    float4 wv = *(const float4*)&w0t[c][o4];
                    acc[o4 + 0] = fmaf(wv.x, fc, acc[o4 + 0]);
                    acc[o4 + 1] = fmaf(wv.y, fc, acc[o4 + 1]);
                    acc[o4 + 2] = fmaf(wv.z, fc, acc[o4 + 2]);
                    acc[o4 + 3] = fmaf(wv.w, fc, acc[o4 + 3]);
                }
            }
            float* op = g_F0 + ((size_t)b * NPTS + j) * 64;
#pragma unroll
            for (int o4 = 0; o4 < 64; o4 += 4)
                *(float4*)(op + o4) = make_float4(acc[o4], acc[o4+1], acc[o4+2], acc[o4+3]);
        }

        __threadfence();
        __syncthreads();
        if (tid == 0) atomicAdd(&g_f0done[b], 1u);
        return;
    }

    // =================================================================
    // ROLE 3: worker — wait for data, in-block ballq, fused MLP+maxpool
    // =================================================================
    {
        const int g = bid - 72;
        const int b = g >> 8;
        const int s0 = (g & 255) * 8;

        float* sW1 = sm;                       // [c][o] 64x64
        float* sW2 = sm + 4096;                // [c][o] 64x128
        float* sX0 = sm + 12288;               // [c][m] 64 x XROW
        float* sX1 = sm + 12288 + 64 * XROW;
        float4* sWXB = (float4*)(sm + 12288 + 128 * XROW);
        float* sB1 = sm + 12288 + 128 * XROW + 256;
        float* sB2 = sB1 + 64;
        __shared__ int s_bq[8][NSAMP];

        // ---- load weights while waiting is pending ----
        for (int i = tid; i < 4096; i += MLPT) {
            int c = i >> 6, o = i & 63;
            sW1[c * 64 + o] = w1[o * 64 + c];
        }
        for (int i = tid; i < 8192; i += MLPT) {
            int c = i >> 7, o = i & 127;
            sW2[c * 128 + o] = w2[o * 64 + c];
        }
        if (tid < 64) {
            sWXB[tid] = make_float4(w0[tid * C0IN + 0], w0[tid * C0IN + 1],
                                    w0[tid * C0IN + 2], b0[tid]);
            sB1[tid] = b1[tid];
        }
        if (tid < 128) sB2[tid] = b2[tid];

        // ---- wait for FPS centers + F0 of this batch ----
        if (tid == 0) {
            while (ld_acq(&g_progress[b]) < (unsigned)(s0 + 8)) __nanosleep(256);
            while (ld_acq(&g_f0done[b]) < 8u) __nanosleep(256);
        }
        __syncthreads();

        // ---- in-block ball query: warp w handles center s0+w ----
        {
            const int lane = tid & 31, w = tid >> 5;
            if (w < 8) {
                const int sg = s0 + w;
                const float* cz = new_xyz + ((size_t)b * NCTR + sg) * 3;
                const float cx = cz[0], cy = cz[1], czz = cz[2];
                const float* pb = pos + (size_t)b * NPTS * 3;

                int cnt = 0, first = -1;
                for (int j0 = 0; j0 < NPTS; j0 += 32) {
                    int j = j0 + lane;
                    float dx = pb[3 * j + 0] - cx;
                    float dy = pb[3 * j + 1] - cy;
                    float dz = pb[3 * j + 2] - czz;
                    float d = fmaf(dz, dz, fmaf(dy, dy, dx * dx));
                    bool hit = d < R2;
                    unsigned bal = __ballot_sync(0xffffffffu, hit);
                    if (bal) {
                        if (first < 0) first = j0 + __ffs((int)bal) - 1;
                        int pre = __popc(bal & ((1u << lane) - 1u));
                        if (hit && cnt + pre < NSAMP) s_bq[w][cnt + pre] = j;
                        cnt += __popc(bal);
                        if (cnt >= NSAMP) break;
                    }
                }
                if (cnt < NSAMP) {
                    int pad = (first < 0) ? 0 : first;
                    if (lane >= cnt) s_bq[w][lane] = pad;
                }
            }
        }
        __syncthreads();

        // ---- phase A: build X0 (layer0 output), 256 rows x 64 ch ----
        {
            const int r = tid >> 1;
            const int h = tid & 1;
            const int o0 = h * 32;
            const int ci = r >> 5, k = r & 31;
            const int sg = s0 + ci;
            const int j = s_bq[ci][k];

            const float* pp = pos + ((size_t)b * NPTS + j) * 3;
            const float* cz = new_xyz + ((size_t)b * NCTR + sg) * 3;
            float rx = pp[0] - cz[0];
            float ry = pp[1] - cz[1];
            float rz = pp[2] - cz[2];
            const float* fp = g_F0 + ((size_t)b * NPTS + j) * 64 + o0;

#pragma unroll
            for (int o4 = 0; o4 < 32; o4 += 4) {
                float4 f = *(const float4*)(fp + o4);
                float fv[4] = { f.x, f.y, f.z, f.w };
#pragma unroll
                for (int i = 0; i < 4; i++) {
                    float4 wb = sWXB[o0 + o4 + i];
                    float v = fv[i] + wb.x * rx + wb.y * ry + wb.z * rz + wb.w;
                    sX0[(o0 + o4 + i) * XROW + r] = fmaxf(v, 0.0f);
                }
            }
        }
        __syncthreads();

        const int tm = tid & 63, tn = tid >> 6;
        const int m0 = tm * 4;

        // ---- GEMM1: X1 = relu(X0 @ W1^T + b1), 256x64, f32x2 ----
        {
            const int n0 = tn * 8;
            unsigned long long acc2[16];
#pragma unroll
            for (int i = 0; i < 16; i++) acc2[i] = 0ULL;

#pragma unroll 8
            for (int c = 0; c < 64; c++) {
                float4 a  = *(const float4*)&sX0[c * XROW + m0];
                float4 bA = *(const float4*)&sW1[c * 64 + n0];
                float4 bB = *(const float4*)&sW1[c * 64 + n0 + 4];
                unsigned long long bp[4] = { pk2(bA.x, bA.y), pk2(bA.z, bA.w),
                                             pk2(bB.x, bB.y), pk2(bB.z, bB.w) };
                unsigned long long ap[4] = { pkb(a.x), pkb(a.y), pkb(a.z), pkb(a.w) };
#pragma unroll
                for (int i = 0; i < 4; i++)
#pragma unroll
                    for (int jp = 0; jp < 4; jp++)
                        F2FMA(acc2[i * 4 + jp], ap[i], bp[jp], acc2[i * 4 + jp]);
            }

#pragma unroll
            for (int jp = 0; jp < 4; jp++) {
                float lo[4], hi[4];
#pragma unroll
                for (int i = 0; i < 4; i++) upk2(acc2[i * 4 + jp], lo[i], hi[i]);
                float bb0 = sB1[n0 + 2 * jp], bb1 = sB1[n0 + 2 * jp + 1];
                float4 v0, v1;
                v0.x = fmaxf(lo[0] + bb0, 0.0f); v0.y = fmaxf(lo[1] + bb0, 0.0f);
                v0.z = fmaxf(lo[2] + bb0, 0.0f); v0.w = fmaxf(lo[3] + bb0, 0.0f);
                v1.x = fmaxf(hi[0] + bb1, 0.0f); v1.y = fmaxf(hi[1] + bb1, 0.0f);
                v1.z = fmaxf(hi[2] + bb1, 0.0f); v1.w = fmaxf(hi[3] + bb1, 0.0f);
                *(float4*)&sX1[(n0 + 2 * jp)     * XROW + m0] = v0;
                *(float4*)&sX1[(n0 + 2 * jp + 1) * XROW + m0] = v1;
            }
        }
        __syncthreads();

        // ---- GEMM2: 256x128, f32x2, fold max+bias+relu ----
        {
            const int n2 = tn * 16;
            unsigned long long acc2[32];
#pragma unroll
            for (int i = 0; i < 32; i++) acc2[i] = 0ULL;

#pragma unroll 4
            for (int c = 0; c < 64; c++) {
                float4 a = *(const float4*)&sX1[c * XROW + m0];
                unsigned long long ap[4] = { pkb(a.x), pkb(a.y), pkb(a.z), pkb(a.w) };
                unsigned long long bp[8];
#pragma unroll
                for (int q = 0; q < 4; q++) {
                    float4 bb = *(const float4*)&sW2[c * 128 + n2 + 4 * q];
                    bp[2 * q]     = pk2(bb.x, bb.y);
                    bp[2 * q + 1] = pk2(bb.z, bb.w);
                }
#pragma unroll
                for (int i = 0; i < 4; i++)
#pragma unroll
                    for (int jp = 0; jp < 8; jp++)
                        F2FMA(acc2[i * 8 + jp], ap[i], bp[jp], acc2[i * 8 + jp]);
            }

            const int center = tm >> 3;
#pragma unroll
            for (int jp = 0; jp < 8; jp++) {
                float lo[4], hi[4];
#pragma unroll
                for (int i = 0; i < 4; i++) upk2(acc2[i * 8 + jp], lo[i], hi[i]);
                float vlo = fmaxf(fmaxf(lo[0], lo[1]), fmaxf(lo[2], lo[3]));
                float vhi = fmaxf(fmaxf(hi[0], hi[1]), fmaxf(hi[2], hi[3]));
                vlo = fmaxf(vlo, __shfl_xor_sync(0xffffffffu, vlo, 1));
                vhi = fmaxf(vhi, __shfl_xor_sync(0xffffffffu, vhi, 1));
                vlo = fmaxf(vlo, __shfl_xor_sync(0xffffffffu, vlo, 2));
                vhi = fmaxf(vhi, __shfl_xor_sync(0xffffffffu, vhi, 2));
                vlo = fmaxf(vlo, __shfl_xor_sync(0xffffffffu, vlo, 4));
                vhi = fmaxf(vhi, __shfl_xor_sync(0xffffffffu, vhi, 4));
                if ((tm & 7) == 0) {
                    int n = n2 + 2 * jp;
                    out_feat[((size_t)b * C2 + n)     * NCTR + (s0 + center)] =
                        fmaxf(vlo + sB2[n], 0.0f);
                    out_feat[((size_t)b * C2 + n + 1) * NCTR + (s0 + center)] =
                        fmaxf(vhi + sB2[n + 1], 0.0f);
                }
            }
        }
    }
}

// =====================================================================
extern "C" void kernel_launch(void* const* d_in, const int* in_sizes, int n_in,
                              void* d_out, int out_size)
{
    const float* pos      = (const float*)d_in[0];
    const float* features = (const float*)d_in[1];
    const float* w0       = (const float*)d_in[2];
    const float* b0       = (const float*)d_in[3];
    const float* w1       = (const float*)d_in[4];
    const float* b1       = (const float*)d_in[5];
    const float* w2       = (const float*)d_in[6];
    const float* b2       = (const float*)d_in[7];

    float* out = (float*)d_out;
    float* new_xyz  = out;                               // (8, 2048, 3)
    float* out_feat = out + (size_t)BATCH * NCTR * 3;    // (8, 128, 2048)

    reset_kernel<<<1, 32>>>();

    cudaFuncSetAttribute(mega_kernel,
                         cudaFuncAttributeMaxDynamicSharedMemorySize,
                         SMEM_FLOATS * sizeof(float));
    mega_kernel<<<GRID_TOTAL, MLPT, SMEM_FLOATS * sizeof(float)>>>(
        pos, features, w0, b0, w1, b1, w2, b2, new_xyz, out_feat);
}